// round 15
// baseline (speedup 1.0000x reference)
#include <cuda_runtime.h>
#include <math.h>
#include <stdint.h>

#define NB 4
#define NT 512
#define DMODEL 769
#define DINNER 1538
#define DSTATE 64
#define DTRANK 49
#define BT (NB*NT)            // 2048 rows
#define XPROJ_N 177           // DT_RANK + 2*D_STATE
#define LDA_IN 800            // padded ld (25 k-tiles of 32)
#define LDA_OUT 1568          // padded ld (49 k-tiles of 32)

// ---------------- scratch (static device globals; zero-initialized) -------------
__device__ float g_xT [NB*64*NT];
__device__ float g_h0 [NB*128*NT];
__device__ float g_h2 [NB*768*NT];
__device__ float g_h  [BT*DMODEL];
__device__ __align__(16) float g_unp [BT*LDA_IN];         // rmsnorm out (rna tf32) / layernorm out
__device__ __align__(16) float g_wi  [2*2*DINNER*LDA_IN]; // in_proj W padded (rna)
__device__ __align__(16) float g_wo  [2*DMODEL*LDA_OUT];  // out_proj W padded (rna)
__device__ __align__(16) float g_wx  [2*XPROJ_N*LDA_OUT]; // x_proj W padded (rna)
__device__ __align__(16) float g_xinp[BT*LDA_OUT];        // dwconv out, padded (rna)
__device__ __align__(16) float g_yp  [BT*LDA_OUT];        // scan out, padded (rna)
__device__ __align__(16) float g_dtA [BT*64];             // x_proj dt-cols (rna), padded
__device__ __align__(16) float g_bc  [BT*128];            // B/C interleaved for scan
__device__ __align__(16) float g_du  [BT*2*DINNER];       // (dt, u) interleaved for scan
__device__ float g_xz [BT*2*DINNER];

__device__ __forceinline__ float silu_f(float v){ return v / (1.f + __expf(-v)); }
__device__ __forceinline__ float tf32r(float v){
    uint32_t r; asm("cvt.rna.tf32.f32 %0, %1;" : "=r"(r) : "f"(v));
    return __uint_as_float(r);
}

// ---- tf32 mma (operands pre-rounded by producers) ----
__device__ __forceinline__ void mma_tf32(float* c, const uint32_t* a, const uint32_t* b){
    asm("mma.sync.aligned.m16n8k8.row.col.f32.tf32.tf32.f32 "
        "{%0,%1,%2,%3}, {%4,%5,%6,%7}, {%8,%9}, {%0,%1,%2,%3};"
        : "+f"(c[0]), "+f"(c[1]), "+f"(c[2]), "+f"(c[3])
        : "r"(a[0]), "r"(a[1]), "r"(a[2]), "r"(a[3]), "r"(b[0]), "r"(b[1]));
}

// ---------------- weight repack into padded layout, rna tf32 rounding -----------
__global__ void k_packw(const float* __restrict__ src, float* __restrict__ dst,
                        int rows, int K, int ldd){
    int idx = blockIdx.x*256 + threadIdx.x;
    if (idx >= rows*K) return;
    int r = idx / K, c = idx - r*K;
    dst[(size_t)r*ldd + c] = tf32r(src[idx]);
}

// ---------------- x (B,T,65) -> g_xT (B,64,T) ----------------
__global__ void k_xt(const float* __restrict__ x){
    __shared__ float tile[32][33];
    int b  = blockIdx.z;
    int t0 = blockIdx.x*32, c0 = blockIdx.y*32;
    int tx = threadIdx.x, ty = threadIdx.y;
    tile[ty][tx] = x[(b*NT + t0 + ty)*65 + c0 + tx];
    __syncthreads();
    g_xT[(b*64 + c0 + ty)*NT + t0 + tx] = tile[tx][ty];
}

// ---------------- front: pointwise conv (64->128) + silu ----------------
__global__ void k_pointconv(const float* __restrict__ pw,
                            const float* __restrict__ pb){
    int idx = blockIdx.x*256 + threadIdx.x;
    int t = idx & 511;
    int c = (idx >> 9) & 127;
    int b = idx >> 16;
    const float* xr = g_xT + b*64*NT + t;
    const float* wr = pw + c*64;
    float acc = pb[c];
#pragma unroll
    for (int i = 0; i < 64; i++) acc += xr[i*NT]*wr[i];
    g_h0[(b*128 + c)*NT + t] = silu_f(acc);
}

// ---- front conv v5: 8 ocs per block, T split in 4 quarters (grid 512) ----
template<int KS>
__global__ void k_conv(const float* __restrict__ w,
                       const float* __restrict__ bias,
                       int ocBase){
    __shared__ float ws[8][8*KS];
    __shared__ float xs[8][160];
    const int tid = threadIdx.x;
    const int b   = blockIdx.x >> 7;
    const int rem = blockIdx.x & 127;
    const int ocg = rem >> 2;
    const int tq  = rem & 3;
    const int oc0 = ocg*8;
    const int tbase = tq*128;
    const int pad = (KS - 1)/2;
    const int oc_sub = tid >> 7;
    const int tc  = tid & 127;

    float acc[4];
#pragma unroll
    for (int ol = 0; ol < 4; ol++) acc[ol] = bias[oc0 + oc_sub*4 + ol];

    for (int icb = 0; icb < 128; icb += 8){
        __syncthreads();
        for (int i = tid; i < 8*155; i += 256){
            int r = i / 155, j = i - r*155;
            int tt = tbase + j - 13;
            const float* hrow = g_h0 + (b*128 + icb + r)*NT;
            xs[r][j] = (tt >= 0 && tt < NT) ? hrow[tt] : 0.f;
        }
        for (int i = tid; i < 8*8*KS; i += 256){
            int oc = i / (8*KS), j = i - oc*(8*KS);
            ws[oc][j] = w[(oc0 + oc)*128*KS + icb*KS + j];
        }
        __syncthreads();
#pragma unroll
        for (int r = 0; r < 8; r++){
            float xv[KS];
            const int base = tc + 13 - pad;
#pragma unroll
            for (int q = 0; q < KS; q++) xv[q] = xs[r][base + q];
#pragma unroll
            for (int ol = 0; ol < 4; ol++){
                const float* wr = &ws[oc_sub*4 + ol][r*KS];
#pragma unroll
                for (int k = 0; k < KS; k++) acc[ol] += wr[k]*xv[k];
            }
        }
    }
#pragma unroll
    for (int ol = 0; ol < 4; ol++)
        g_h2[(b*768 + ocBase + oc0 + oc_sub*4 + ol)*NT + tbase + tc] = silu_f(acc[ol]);
}

// ---------------- (B,C,T) -> (B,T,769) transpose ----------------
__global__ void k_transpose(){
    __shared__ float tile[32][33];
    int b  = blockIdx.z;
    int t0 = blockIdx.x*32, c0 = blockIdx.y*32;
    int tx = threadIdx.x, ty = threadIdx.y;
    tile[ty][tx] = g_h2[(b*768 + c0 + ty)*NT + t0 + tx];
    __syncthreads();
    g_h[(b*NT + t0 + ty)*DMODEL + c0 + tx] = tile[tx][ty];
}

__global__ void k_pe(const float* __restrict__ x){
    int i = blockIdx.x*256 + threadIdx.x;
    if (i >= BT) return;
    g_h[i*DMODEL + 768] = x[i*65 + 64];
}

// ---------------- rmsnorm (rna tf32 out, padded) / layernorm (exact) ------------
__global__ void k_rmsnorm(const float* __restrict__ w){
    int m = blockIdx.x, tid = threadIdx.x;
    const float* row = g_h + m*DMODEL;
    float s = 0.f;
    for (int k = tid; k < DMODEL; k += 256){ float v = row[k]; s += v*v; }
#pragma unroll
    for (int o = 16; o > 0; o >>= 1) s += __shfl_xor_sync(0xffffffffu, s, o);
    __shared__ float red[8];
    if ((tid & 31) == 0) red[tid >> 5] = s;
    __syncthreads();
    s = red[0]+red[1]+red[2]+red[3]+red[4]+red[5]+red[6]+red[7];
    float sc = rsqrtf(s/769.f + 1e-6f);
    float* o = g_unp + (size_t)m*LDA_IN;
    for (int k = tid; k < DMODEL; k += 256) o[k] = tf32r(row[k]*sc*w[k]);
}

__global__ void k_layernorm(const float* __restrict__ w, const float* __restrict__ bb){
    int m = blockIdx.x, tid = threadIdx.x;
    const float* row = g_h + m*DMODEL;
    float s1 = 0.f, s2 = 0.f;
    for (int k = tid; k < DMODEL; k += 256){ float v = row[k]; s1 += v; s2 += v*v; }
#pragma unroll
    for (int o = 16; o > 0; o >>= 1){
        s1 += __shfl_xor_sync(0xffffffffu, s1, o);
        s2 += __shfl_xor_sync(0xffffffffu, s2, o);
    }
    __shared__ float r1[8], r2[8];
    if ((tid & 31) == 0){ r1[tid >> 5] = s1; r2[tid >> 5] = s2; }
    __syncthreads();
    s1 = 0.f; s2 = 0.f;
#pragma unroll
    for (int i = 0; i < 8; i++){ s1 += r1[i]; s2 += r2[i]; }
    float mean = s1/769.f;
    float var  = s2/769.f - mean*mean;
    float istd = rsqrtf(var + 1e-5f);
    float* o = g_unp + (size_t)m*LDA_IN;
    for (int k = tid; k < DMODEL; k += 256)
        o[k] = (row[k] - mean)*istd*w[k] + bb[k];
}

// ---------------- tf32 MMA GEMM 128xBNx32, row-major smem (conflict-free) -------
// NJ = BN/16. Padded zero-filled operands.
// epi: 0 = store, 2 = C += acc,
//      3 = x_proj scatter: gn<49 -> C (dtA, ld 64, rna); else B/C interleave -> C2
template<int NJ>
__global__ void __launch_bounds__(256, 2)
k_mma128(const float* __restrict__ A, int lda,
         const float* __restrict__ W, int ldw,
         float* __restrict__ C, int ldc,
         int M, int N, int K, int epi,
         float* __restrict__ C2){
    __shared__ __align__(16) float As[128][36];
    __shared__ __align__(16) float Ws[NJ*16][36];
    const int BN = NJ*16;

    const int tid  = threadIdx.x;
    const int lane = tid & 31;
    const int wid  = tid >> 5;
    const int warp_m = wid & 3, warp_n = wid >> 2;
    const int m0 = blockIdx.y*128, n0 = blockIdx.x*BN;

    const int sr  = tid >> 1;
    const int skb = (tid & 1) * 16;

    const bool okA = (m0 + sr) < M;
    const bool stW = (sr < BN);
    const bool okW = stW && ((n0 + sr) < N);
    const float* Arow = A + (size_t)(m0 + sr)*lda + skb;
    const float* Wrow = W + (size_t)(n0 + sr)*ldw + skb;

    float acc[2][NJ][4];
#pragma unroll
    for (int i = 0; i < 2; i++)
#pragma unroll
        for (int j = 0; j < NJ; j++)
#pragma unroll
            for (int q = 0; q < 4; q++) acc[i][j][q] = 0.f;

    const int nk = (K + 31) >> 5;
    float4 ra4[4], rb4[4];

#pragma unroll
    for (int q = 0; q < 4; q++){
        ra4[q] = okA ? ((const float4*)Arow)[q] : make_float4(0.f,0.f,0.f,0.f);
        rb4[q] = okW ? ((const float4*)Wrow)[q] : make_float4(0.f,0.f,0.f,0.f);
    }

    const int r_f = lane >> 2;
    const int c_f = lane & 3;

    for (int kt = 0; kt < nk; kt++){
        __syncthreads();
#pragma unroll
        for (int q = 0; q < 4; q++)
            *(float4*)&As[sr][skb + q*4] = ra4[q];
        if (stW){
#pragma unroll
            for (int q = 0; q < 4; q++)
                *(float4*)&Ws[sr][skb + q*4] = rb4[q];
        }
        __syncthreads();

        if (kt + 1 < nk){
            int k0 = (kt + 1)*32;
#pragma unroll
            for (int q = 0; q < 4; q++){
                ra4[q] = okA ? ((const float4*)(Arow + k0))[q] : make_float4(0.f,0.f,0.f,0.f);
                rb4[q] = okW ? ((const float4*)(Wrow + k0))[q] : make_float4(0.f,0.f,0.f,0.f);
            }
        }

#pragma unroll
        for (int kch = 0; kch < 4; kch++){
            uint32_t af[2][4], bf[NJ][2];
#pragma unroll
            for (int i = 0; i < 2; i++){
                const uint32_t* ar = (const uint32_t*)&As[warp_m*32 + i*16 + r_f][kch*8 + c_f];
                af[i][0] = ar[0];
                af[i][1] = ar[8*36];
                af[i][2] = ar[4];
                af[i][3] = ar[8*36 + 4];
            }
#pragma unroll
            for (int j = 0; j < NJ; j++){
                const uint32_t* br = (const uint32_t*)&Ws[warp_n*NJ*8 + j*8 + r_f][kch*8 + c_f];
                bf[j][0] = br[0];
                bf[j][1] = br[4];
            }
#pragma unroll
            for (int i = 0; i < 2; i++)
#pragma unroll
                for (int j = 0; j < NJ; j++) mma_tf32(acc[i][j], af[i], bf[j]);
        }
    }

    const int r_c = lane >> 2, c_c = (lane & 3)*2;
#pragma unroll
    for (int i = 0; i < 2; i++){
        int gmA0 = m0 + warp_m*32 + i*16 + r_c;
#pragma unroll
        for (int j = 0; j < NJ; j++){
            int gn0 = n0 + warp_n*(NJ*8) + j*8 + c_c;
#pragma unroll
            for (int h = 0; h < 2; h++){
                int gm = gmA0 + h*8;
                if (gm >= M) continue;
#pragma unroll
                for (int e = 0; e < 2; e++){
                    int gn = gn0 + e;
                    if (gn >= N) continue;
                    float v = acc[i][j][2*h + e];
                    if (epi == 0){
                        C[(size_t)gm*ldc + gn] = v;
                    } else if (epi == 2){
                        C[(size_t)gm*ldc + gn] += v;
                    } else {  // epi == 3: x_proj scatter
                        if (gn < DTRANK){
                            C[(size_t)gm*64 + gn] = tf32r(v);
                        } else if (gn < DTRANK + DSTATE){
                            int nb = gn - DTRANK;
                            int slot = (nb < 32) ? 2*nb : 2*(nb - 32) + 1;
                            C2[(size_t)gm*128 + slot] = v;
                        } else {
                            int nc = gn - DTRANK - DSTATE;
                            int slot = 64 + ((nc < 32) ? 2*nc : 2*(nc - 32) + 1);
                            C2[(size_t)gm*128 + slot] = v;
                        }
                    }
                }
            }
        }
    }
}

// ---------------- SGEMM 64x64 fp32 (dt GEMM): bias + fast softplus --------------
// writes dt into g_du at stride 2 (slot .x)
__global__ void k_sgemm64(const float* __restrict__ A, int lda,
                          const float* __restrict__ W, int ldw,
                          float* __restrict__ C,
                          int M, int N, int K,
                          const float* __restrict__ bias){
    __shared__ __align__(16) float As[16][68];
    __shared__ __align__(16) float Ws[16][68];
    const int tid = threadIdx.x;
    const int m0 = blockIdx.y*64, n0 = blockIdx.x*64;
    const int tx = tid & 15, ty = tid >> 4;

    float acc[4][4];
#pragma unroll
    for (int i = 0; i < 4; i++)
#pragma unroll
        for (int j = 0; j < 4; j++) acc[i][j] = 0.f;

    for (int k0 = 0; k0 < K; k0 += 16){
        for (int i = tid; i < 1024; i += 256){
            int mm = i >> 4, kk = i & 15;
            int gk = k0 + kk;
            int gm = m0 + mm;
            As[kk][mm] = (gm < M && gk < K) ? A[(size_t)gm*lda + gk] : 0.f;
            int gn = n0 + mm;
            Ws[kk][mm] = (gn < N && gk < K) ? W[(size_t)gn*ldw + gk] : 0.f;
        }
        __syncthreads();
#pragma unroll
        for (int kk = 0; kk < 16; kk++){
            float4 a4 = *(const float4*)&As[kk][ty*4];
            float4 w4 = *(const float4*)&Ws[kk][tx*4];
            float av[4] = {a4.x, a4.y, a4.z, a4.w};
            float wv[4] = {w4.x, w4.y, w4.z, w4.w};
#pragma unroll
            for (int i = 0; i < 4; i++)
#pragma unroll
                for (int j = 0; j < 4; j++) acc[i][j] += av[i]*wv[j];
        }
        __syncthreads();
    }

#pragma unroll
    for (int i = 0; i < 4; i++){
        int gm = m0 + ty*4 + i;
        if (gm >= M) continue;
#pragma unroll
        for (int j = 0; j < 4; j++){
            int gn = n0 + tx*4 + j;
            if (gn >= N) continue;
            float v = acc[i][j] + bias[gn];
            v = fmaxf(v, 0.f) + __logf(1.f + __expf(-fabsf(v)));   // fast softplus
            C[(size_t)gm*(2*DINNER) + 2*gn] = v;                   // du.x
        }
    }
}

// ---------------- depthwise causal conv (k=4) + silu, 2 d per thread ------------
__global__ void k_dwconv(const float* __restrict__ cw, const float* __restrict__ cb){
    int idx = blockIdx.x*256 + threadIdx.x;           // BT*DINNER/2 threads
    int d2 = idx % (DINNER/2);
    int bt = idx / (DINNER/2);
    int d  = d2*2;
    int t  = bt & 511;
    float4 w0 = *(const float4*)&cw[d*4];             // weights for d
    float4 w1 = *(const float4*)&cw[d*4 + 4];         // weights for d+1
    float2 acc = *(const float2*)&cb[d];
    float w0a[4] = {w0.x, w0.y, w0.z, w0.w};
    float w1a[4] = {w1.x, w1.y, w1.z, w1.w};
#pragma unroll
    for (int k = 0; k < 4; k++){
        int tt = t - 3 + k;
        if (tt >= 0){
            float2 xv = *(const float2*)&g_xz[(size_t)(bt - 3 + k)*2*DINNER + d];
            acc.x += w0a[k]*xv.x;
            acc.y += w1a[k]*xv.y;
        }
    }
    float u0 = tf32r(silu_f(acc.x));
    float u1 = tf32r(silu_f(acc.y));
    *(float2*)&g_xinp[(size_t)bt*LDA_OUT + d] = make_float2(u0, u1);
    g_du[(size_t)bt*2*DINNER + 2*d + 1]     = u0;     // du.y for d
    g_du[(size_t)bt*2*DINNER + 2*(d+1) + 1] = u1;     // du.y for d+1
}

// ---------------- selective scan: warp per (b,d), 2 states/lane ----------------
__global__ void k_scan(const float* __restrict__ Alog, const float* __restrict__ Dv){
    int w    = blockIdx.x*4 + (threadIdx.x >> 5);
    int lane = threadIdx.x & 31;
    int b = w & 3;
    int d = w >> 2;

    float A1 = -__expf(Alog[d*64 + lane]);
    float A2 = -__expf(Alog[d*64 + lane + 32]);
    float Dd = Dv[d];
    float h1 = 0.f, h2 = 0.f;

    int r = b*NT;
    for (int t = 0; t < NT; t++, r++){
        float2 du  = *(const float2*)&g_du[(size_t)r*2*DINNER + 2*d];
        float dtv = du.x, uv = du.y;
        float2 B12 = *(const float2*)&g_bc[(size_t)r*128 + 2*lane];
        float2 C12 = *(const float2*)&g_bc[(size_t)r*128 + 64 + 2*lane];
        float dub = dtv*uv;
        h1 = __expf(dtv*A1)*h1 + dub*B12.x;
        h2 = __expf(dtv*A2)*h2 + dub*B12.y;
        float p = h1*C12.x + h2*C12.y;
#pragma unroll
        for (int o = 16; o > 0; o >>= 1) p += __shfl_xor_sync(0xffffffffu, p, o);
        if (lane == 0){
            float zv = g_xz[(size_t)r*2*DINNER + DINNER + d];
            g_yp[(size_t)r*LDA_OUT + d] = tf32r((p + uv*Dd) * silu_f(zv));
        }
    }
}

// ---------------- classifier: warp per (row, class) ----------------
__global__ void k_classifier(const float* __restrict__ ow,
                             const float* __restrict__ ob,
                             float* __restrict__ out){
    int m = blockIdx.x;
    int wid  = threadIdx.x >> 5;
    int lane = threadIdx.x & 31;
    const float* u  = g_unp + (size_t)m*LDA_IN;
    const float* wr = ow + wid*DMODEL;
    float s = 0.f;
    for (int k = lane; k < DMODEL; k += 32) s += u[k]*wr[k];
#pragma unroll
    for (int o = 16; o > 0; o >>= 1) s += __shfl_xor_sync(0xffffffffu, s, o);
    if (lane == 0) out[m*10 + wid] = s + ob[wid];
}

// ---------------- orchestration ----------------
extern "C" void kernel_launch(void* const* d_in, const int* in_sizes, int n_in,
                              void* d_out, int out_size){
    const float* x    = (const float*)d_in[0];
    const float* pw   = (const float*)d_in[1];
    const float* pb   = (const float*)d_in[2];
    const float* c1w  = (const float*)d_in[3];
    const float* c1b  = (const float*)d_in[4];
    const float* c2w  = (const float*)d_in[5];
    const float* c2b  = (const float*)d_in[6];
    const float* c3w  = (const float*)d_in[7];
    const float* c3b  = (const float*)d_in[8];
    const float* lnw  = (const float*)d_in[9];
    const float* lnb  = (const float*)d_in[10];
    const float* ow   = (const float*)d_in[11];
    const float* ob   = (const float*)d_in[12];
    const float* rmsw = (const float*)d_in[13];
    const float* inw  = (const float*)d_in[14];
    const float* dww  = (const float*)d_in[15];
    const float* dwb  = (const float*)d_in[16];
    const float* xpw  = (const float*)d_in[17];
    const float* dtw  = (const float*)d_in[18];
    const float* dtb  = (const float*)d_in[19];
    const float* alog = (const float*)d_in[20];
    const float* dsk  = (const float*)d_in[21];
    const float* opw  = (const float*)d_in[22];

    float *p_unp, *p_xz, *p_xinp, *p_du, *p_yp, *p_h;
    float *p_wi, *p_wo, *p_wx, *p_dtA, *p_bc;
    cudaGetSymbolAddress((void**)&p_unp,  g_unp);
    cudaGetSymbolAddress((void**)&p_xz,   g_xz);
    cudaGetSymbolAddress((void**)&p_xinp, g_xinp);
    cudaGetSymbolAddress((void**)&p_du,   g_du);
    cudaGetSymbolAddress((void**)&p_yp,   g_yp);
    cudaGetSymbolAddress((void**)&p_h,    g_h);
    cudaGetSymbolAddress((void**)&p_wi,   g_wi);
    cudaGetSymbolAddress((void**)&p_wo,   g_wo);
    cudaGetSymbolAddress((void**)&p_wx,   g_wx);
    cudaGetSymbolAddress((void**)&p_dtA,  g_dtA);
    cudaGetSymbolAddress((void**)&p_bc,   g_bc);

    // weight repacks into padded layout, rna tf32 rounding (pads stay zero)
    k_packw<<<(2*2*DINNER*DMODEL + 255)/256, 256>>>(inw, p_wi, 2*2*DINNER, DMODEL, LDA_IN);
    k_packw<<<(2*DMODEL*DINNER + 255)/256, 256>>>(opw, p_wo, 2*DMODEL, DINNER, LDA_OUT);
    k_packw<<<(2*XPROJ_N*DINNER + 255)/256, 256>>>(xpw, p_wx, 2*XPROJ_N, DINNER, LDA_OUT);

    k_xt<<<dim3(16, 2, 4), dim3(32, 32)>>>(x);
    k_pointconv<<<1024, 256>>>(pw, pb);
    k_conv<3> <<<512, 256>>>(c1w, c1b, 0);
    k_conv<9> <<<512, 256>>>(c2w, c2b, 256);
    k_conv<27><<<512, 256>>>(c3w, c3b, 512);
    k_transpose<<<dim3(16, 24, 4), dim3(32, 32)>>>();
    k_pe<<<8, 256>>>(x);

    for (int l = 0; l < 2; l++){
        k_rmsnorm<<<2048, 256>>>(rmsw + l*DMODEL);
        // xz = un @ Wi^T       (2048 x 3076, K=769)  tf32 mma BN=128, 400 blocks
        k_mma128<8><<<dim3(25, 16), 256>>>(p_unp, LDA_IN,
                                        p_wi + (size_t)l*2*DINNER*LDA_IN, LDA_IN,
                                        p_xz, 2*DINNER,
                                        BT, 2*DINNER, DMODEL, 0, nullptr);
        k_dwconv<<<6152, 256>>>(dww + l*DINNER*4, dwb + l*DINNER);
        // dbc = xin @ Wx^T     (2048 x 177, K=1538)  tf32 mma, scatter epilogue
        k_mma128<4><<<dim3(3, 16), 256>>>(p_xinp, LDA_OUT,
                                        p_wx + (size_t)l*XPROJ_N*LDA_OUT, LDA_OUT,
                                        p_dtA, 64,
                                        BT, XPROJ_N, DINNER, 3, p_bc);
        // dt = softplus(dtA @ Wdt^T + bdt) -> g_du.x   (K=49, fp32 64x64)
        k_sgemm64<<<dim3(25, 32), 256>>>(p_dtA, 64,
                                         dtw + (size_t)l*DINNER*DTRANK, DTRANK,
                                         p_du,
                                         BT, DINNER, DTRANK, dtb + l*DINNER);
        k_scan<<<1538, 128>>>(alog + (size_t)l*DINNER*DSTATE, dsk + l*DINNER);
        // h += y @ Wo^T        (2048 x 769, K=1538)  tf32 mma BN=64, 208 blocks
        k_mma128<4><<<dim3(13, 16), 256>>>(p_yp, LDA_OUT,
                                       p_wo + (size_t)l*DMODEL*LDA_OUT, LDA_OUT,
                                       p_h, DMODEL,
                                       BT, DMODEL, DINNER, 2, nullptr);
    }

    k_layernorm<<<2048, 256>>>(lnw, lnb);
    k_classifier<<<2048, 320>>>(ow, ob, (float*)d_out);
}

// round 16
// speedup vs baseline: 1.0081x; 1.0081x over previous
#include <cuda_runtime.h>
#include <math.h>
#include <stdint.h>

#define NB 4
#define NT 512
#define DMODEL 769
#define DINNER 1538
#define DSTATE 64
#define DTRANK 49
#define BT (NB*NT)            // 2048 rows
#define XPROJ_N 177           // DT_RANK + 2*D_STATE
#define LDA_IN 800            // padded ld (25 k-tiles of 32)
#define LDA_OUT 1568          // padded ld (49 k-tiles of 32)

// ---------------- scratch (static device globals; zero-initialized) -------------
__device__ float g_xT [NB*64*NT];
__device__ float g_h0 [NB*128*NT];
__device__ float g_h2 [NB*768*NT];
__device__ float g_h  [BT*DMODEL];
__device__ __align__(16) float g_unp [BT*LDA_IN];         // rmsnorm out (rna tf32) / layernorm out
__device__ __align__(16) float g_wi  [2*2*DINNER*LDA_IN]; // in_proj W padded (rna)
__device__ __align__(16) float g_wo  [2*DMODEL*LDA_OUT];  // out_proj W padded (rna)
__device__ __align__(16) float g_wx  [2*XPROJ_N*LDA_OUT]; // x_proj W padded (rna)
__device__ __align__(16) float g_xinp[BT*LDA_OUT];        // dwconv out, padded (rna)
__device__ __align__(16) float g_yp  [BT*LDA_OUT];        // scan out, padded (rna)
__device__ __align__(16) float g_dtA [BT*64];             // x_proj dt-cols (rna), padded
__device__ __align__(16) float g_bc  [BT*128];            // B/C interleaved for scan
__device__ __align__(16) float g_du  [BT*2*DINNER];       // (dt, u) interleaved for scan
__device__ float g_xz [BT*2*DINNER];

__device__ __forceinline__ float silu_f(float v){ return v / (1.f + __expf(-v)); }
__device__ __forceinline__ float tf32r(float v){
    uint32_t r; asm("cvt.rna.tf32.f32 %0, %1;" : "=r"(r) : "f"(v));
    return __uint_as_float(r);
}

// ---- tf32 mma (operands pre-rounded by producers) ----
__device__ __forceinline__ void mma_tf32(float* c, const uint32_t* a, const uint32_t* b){
    asm("mma.sync.aligned.m16n8k8.row.col.f32.tf32.tf32.f32 "
        "{%0,%1,%2,%3}, {%4,%5,%6,%7}, {%8,%9}, {%0,%1,%2,%3};"
        : "+f"(c[0]), "+f"(c[1]), "+f"(c[2]), "+f"(c[3])
        : "r"(a[0]), "r"(a[1]), "r"(a[2]), "r"(a[3]), "r"(b[0]), "r"(b[1]));
}

// ---------------- weight repack into padded layout, rna tf32 rounding -----------
__global__ void k_packw(const float* __restrict__ src, float* __restrict__ dst,
                        int rows, int K, int ldd){
    int idx = blockIdx.x*256 + threadIdx.x;
    if (idx >= rows*K) return;
    int r = idx / K, c = idx - r*K;
    dst[(size_t)r*ldd + c] = tf32r(src[idx]);
}

// ---------------- x (B,T,65) -> g_xT (B,64,T) ----------------
__global__ void k_xt(const float* __restrict__ x){
    __shared__ float tile[32][33];
    int b  = blockIdx.z;
    int t0 = blockIdx.x*32, c0 = blockIdx.y*32;
    int tx = threadIdx.x, ty = threadIdx.y;
    tile[ty][tx] = x[(b*NT + t0 + ty)*65 + c0 + tx];
    __syncthreads();
    g_xT[(b*64 + c0 + ty)*NT + t0 + tx] = tile[tx][ty];
}

// ---------------- front: pointwise conv (64->128) + silu ----------------
__global__ void k_pointconv(const float* __restrict__ pw,
                            const float* __restrict__ pb){
    int idx = blockIdx.x*256 + threadIdx.x;
    int t = idx & 511;
    int c = (idx >> 9) & 127;
    int b = idx >> 16;
    const float* xr = g_xT + b*64*NT + t;
    const float* wr = pw + c*64;
    float acc = pb[c];
#pragma unroll
    for (int i = 0; i < 64; i++) acc += xr[i*NT]*wr[i];
    g_h0[(b*128 + c)*NT + t] = silu_f(acc);
}

// ---- front conv v5: 8 ocs per block, T split in 4 quarters (grid 512) ----
template<int KS>
__global__ void k_conv(const float* __restrict__ w,
                       const float* __restrict__ bias,
                       int ocBase){
    __shared__ float ws[8][8*KS];
    __shared__ float xs[8][160];
    const int tid = threadIdx.x;
    const int b   = blockIdx.x >> 7;
    const int rem = blockIdx.x & 127;
    const int ocg = rem >> 2;
    const int tq  = rem & 3;
    const int oc0 = ocg*8;
    const int tbase = tq*128;
    const int pad = (KS - 1)/2;
    const int oc_sub = tid >> 7;
    const int tc  = tid & 127;

    float acc[4];
#pragma unroll
    for (int ol = 0; ol < 4; ol++) acc[ol] = bias[oc0 + oc_sub*4 + ol];

    for (int icb = 0; icb < 128; icb += 8){
        __syncthreads();
        for (int i = tid; i < 8*155; i += 256){
            int r = i / 155, j = i - r*155;
            int tt = tbase + j - 13;
            const float* hrow = g_h0 + (b*128 + icb + r)*NT;
            xs[r][j] = (tt >= 0 && tt < NT) ? hrow[tt] : 0.f;
        }
        for (int i = tid; i < 8*8*KS; i += 256){
            int oc = i / (8*KS), j = i - oc*(8*KS);
            ws[oc][j] = w[(oc0 + oc)*128*KS + icb*KS + j];
        }
        __syncthreads();
#pragma unroll
        for (int r = 0; r < 8; r++){
            float xv[KS];
            const int base = tc + 13 - pad;
#pragma unroll
            for (int q = 0; q < KS; q++) xv[q] = xs[r][base + q];
#pragma unroll
            for (int ol = 0; ol < 4; ol++){
                const float* wr = &ws[oc_sub*4 + ol][r*KS];
#pragma unroll
                for (int k = 0; k < KS; k++) acc[ol] += wr[k]*xv[k];
            }
        }
    }
#pragma unroll
    for (int ol = 0; ol < 4; ol++)
        g_h2[(b*768 + ocBase + oc0 + oc_sub*4 + ol)*NT + tbase + tc] = silu_f(acc[ol]);
}

// ---------------- (B,C,T) -> (B,T,769) transpose ----------------
__global__ void k_transpose(){
    __shared__ float tile[32][33];
    int b  = blockIdx.z;
    int t0 = blockIdx.x*32, c0 = blockIdx.y*32;
    int tx = threadIdx.x, ty = threadIdx.y;
    tile[ty][tx] = g_h2[(b*768 + c0 + ty)*NT + t0 + tx];
    __syncthreads();
    g_h[(b*NT + t0 + ty)*DMODEL + c0 + tx] = tile[tx][ty];
}

__global__ void k_pe(const float* __restrict__ x){
    int i = blockIdx.x*256 + threadIdx.x;
    if (i >= BT) return;
    g_h[i*DMODEL + 768] = x[i*65 + 64];
}

// ---------------- rmsnorm (rna tf32 out, padded) / layernorm (exact) ------------
__global__ void k_rmsnorm(const float* __restrict__ w){
    int m = blockIdx.x, tid = threadIdx.x;
    const float* row = g_h + m*DMODEL;
    float s = 0.f;
    for (int k = tid; k < DMODEL; k += 256){ float v = row[k]; s += v*v; }
#pragma unroll
    for (int o = 16; o > 0; o >>= 1) s += __shfl_xor_sync(0xffffffffu, s, o);
    __shared__ float red[8];
    if ((tid & 31) == 0) red[tid >> 5] = s;
    __syncthreads();
    s = red[0]+red[1]+red[2]+red[3]+red[4]+red[5]+red[6]+red[7];
    float sc = rsqrtf(s/769.f + 1e-6f);
    float* o = g_unp + (size_t)m*LDA_IN;
    for (int k = tid; k < DMODEL; k += 256) o[k] = tf32r(row[k]*sc*w[k]);
}

__global__ void k_layernorm(const float* __restrict__ w, const float* __restrict__ bb){
    int m = blockIdx.x, tid = threadIdx.x;
    const float* row = g_h + m*DMODEL;
    float s1 = 0.f, s2 = 0.f;
    for (int k = tid; k < DMODEL; k += 256){ float v = row[k]; s1 += v; s2 += v*v; }
#pragma unroll
    for (int o = 16; o > 0; o >>= 1){
        s1 += __shfl_xor_sync(0xffffffffu, s1, o);
        s2 += __shfl_xor_sync(0xffffffffu, s2, o);
    }
    __shared__ float r1[8], r2[8];
    if ((tid & 31) == 0){ r1[tid >> 5] = s1; r2[tid >> 5] = s2; }
    __syncthreads();
    s1 = 0.f; s2 = 0.f;
#pragma unroll
    for (int i = 0; i < 8; i++){ s1 += r1[i]; s2 += r2[i]; }
    float mean = s1/769.f;
    float var  = s2/769.f - mean*mean;
    float istd = rsqrtf(var + 1e-5f);
    float* o = g_unp + (size_t)m*LDA_IN;
    for (int k = tid; k < DMODEL; k += 256)
        o[k] = (row[k] - mean)*istd*w[k] + bb[k];
}

// ---------------- tf32 MMA GEMM 128xBNx32, conflict-free smem, double-buffered --
// NJ = BN/16. Padded zero-filled operands. Dynamic smem:
//   A[2][128*36] then W[2][NJ*16*36] floats.
// epi: 0 = store, 2 = C += acc,
//      3 = x_proj scatter: gn<49 -> C (dtA, ld 64, rna); else B/C interleave -> C2
template<int NJ>
__global__ void __launch_bounds__(256, 2)
k_mma128(const float* __restrict__ A, int lda,
         const float* __restrict__ W, int ldw,
         float* __restrict__ C, int ldc,
         int M, int N, int K, int epi,
         float* __restrict__ C2){
    extern __shared__ float smem[];
    const int BN   = NJ*16;
    const int A_SZ = 128*36;
    const int W_SZ = BN*36;
    float* Abuf = smem;                 // [2][A_SZ]
    float* Wbuf = smem + 2*A_SZ;        // [2][W_SZ]

    const int tid  = threadIdx.x;
    const int lane = tid & 31;
    const int wid  = tid >> 5;
    const int warp_m = wid & 3, warp_n = wid >> 2;
    const int m0 = blockIdx.y*128, n0 = blockIdx.x*BN;

    const int sr  = tid >> 1;
    const int skb = (tid & 1) * 16;

    const bool okA = (m0 + sr) < M;
    const bool stW = (sr < BN);
    const bool okW = stW && ((n0 + sr) < N);
    const float* Arow = A + (size_t)(m0 + sr)*lda + skb;
    const float* Wrow = W + (size_t)(n0 + sr)*ldw + skb;

    float acc[2][NJ][4];
#pragma unroll
    for (int i = 0; i < 2; i++)
#pragma unroll
        for (int j = 0; j < NJ; j++)
#pragma unroll
            for (int q = 0; q < 4; q++) acc[i][j][q] = 0.f;

    const int nk = (K + 31) >> 5;
    float4 ra4[4], rb4[4];

    // prefetch + store tile 0 into buffer 0
#pragma unroll
    for (int q = 0; q < 4; q++){
        ra4[q] = okA ? ((const float4*)Arow)[q] : make_float4(0.f,0.f,0.f,0.f);
        rb4[q] = okW ? ((const float4*)Wrow)[q] : make_float4(0.f,0.f,0.f,0.f);
    }
#pragma unroll
    for (int q = 0; q < 4; q++)
        *(float4*)&Abuf[sr*36 + skb + q*4] = ra4[q];
    if (stW){
#pragma unroll
        for (int q = 0; q < 4; q++)
            *(float4*)&Wbuf[sr*36 + skb + q*4] = rb4[q];
    }
    __syncthreads();

    const int r_f = lane >> 2;
    const int c_f = lane & 3;

    int buf = 0;
    for (int kt = 0; kt < nk; kt++){
        // prefetch next tile from global (latency overlapped by mma below)
        if (kt + 1 < nk){
            int k0 = (kt + 1)*32;
#pragma unroll
            for (int q = 0; q < 4; q++){
                ra4[q] = okA ? ((const float4*)(Arow + k0))[q] : make_float4(0.f,0.f,0.f,0.f);
                rb4[q] = okW ? ((const float4*)(Wrow + k0))[q] : make_float4(0.f,0.f,0.f,0.f);
            }
        }

        const float* Ab = Abuf + buf*A_SZ;
        const float* Wb = Wbuf + buf*W_SZ;
#pragma unroll
        for (int kch = 0; kch < 4; kch++){
            uint32_t af[2][4], bf[NJ][2];
#pragma unroll
            for (int i = 0; i < 2; i++){
                const uint32_t* ar = (const uint32_t*)&Ab[(warp_m*32 + i*16 + r_f)*36 + kch*8 + c_f];
                af[i][0] = ar[0];
                af[i][1] = ar[8*36];
                af[i][2] = ar[4];
                af[i][3] = ar[8*36 + 4];
            }
#pragma unroll
            for (int j = 0; j < NJ; j++){
                const uint32_t* br = (const uint32_t*)&Wb[(warp_n*NJ*8 + j*8 + r_f)*36 + kch*8 + c_f];
                bf[j][0] = br[0];
                bf[j][1] = br[4];
            }
#pragma unroll
            for (int i = 0; i < 2; i++)
#pragma unroll
                for (int j = 0; j < NJ; j++) mma_tf32(acc[i][j], af[i], bf[j]);
        }

        // store next tile into the other buffer (no racer: that buffer was
        // fully consumed before the sync that ended iteration kt-1)
        if (kt + 1 < nk){
            int nb = buf ^ 1;
            float* An = Abuf + nb*A_SZ;
            float* Wn = Wbuf + nb*W_SZ;
#pragma unroll
            for (int q = 0; q < 4; q++)
                *(float4*)&An[sr*36 + skb + q*4] = ra4[q];
            if (stW){
#pragma unroll
                for (int q = 0; q < 4; q++)
                    *(float4*)&Wn[sr*36 + skb + q*4] = rb4[q];
            }
            __syncthreads();
            buf = nb;
        }
    }

    const int r_c = lane >> 2, c_c = (lane & 3)*2;
#pragma unroll
    for (int i = 0; i < 2; i++){
        int gmA0 = m0 + warp_m*32 + i*16 + r_c;
#pragma unroll
        for (int j = 0; j < NJ; j++){
            int gn0 = n0 + warp_n*(NJ*8) + j*8 + c_c;
#pragma unroll
            for (int h = 0; h < 2; h++){
                int gm = gmA0 + h*8;
                if (gm >= M) continue;
#pragma unroll
                for (int e = 0; e < 2; e++){
                    int gn = gn0 + e;
                    if (gn >= N) continue;
                    float v = acc[i][j][2*h + e];
                    if (epi == 0){
                        C[(size_t)gm*ldc + gn] = v;
                    } else if (epi == 2){
                        C[(size_t)gm*ldc + gn] += v;
                    } else {  // epi == 3: x_proj scatter
                        if (gn < DTRANK){
                            C[(size_t)gm*64 + gn] = tf32r(v);
                        } else if (gn < DTRANK + DSTATE){
                            int nb2 = gn - DTRANK;
                            int slot = (nb2 < 32) ? 2*nb2 : 2*(nb2 - 32) + 1;
                            C2[(size_t)gm*128 + slot] = v;
                        } else {
                            int nc = gn - DTRANK - DSTATE;
                            int slot = 64 + ((nc < 32) ? 2*nc : 2*(nc - 32) + 1);
                            C2[(size_t)gm*128 + slot] = v;
                        }
                    }
                }
            }
        }
    }
}

// ---------------- SGEMM 64x64 fp32 (dt GEMM): bias + fast softplus --------------
// writes dt into g_du at stride 2 (slot .x)
__global__ void k_sgemm64(const float* __restrict__ A, int lda,
                          const float* __restrict__ W, int ldw,
                          float* __restrict__ C,
                          int M, int N, int K,
                          const float* __restrict__ bias){
    __shared__ __align__(16) float As[16][68];
    __shared__ __align__(16) float Ws[16][68];
    const int tid = threadIdx.x;
    const int m0 = blockIdx.y*64, n0 = blockIdx.x*64;
    const int tx = tid & 15, ty = tid >> 4;

    float acc[4][4];
#pragma unroll
    for (int i = 0; i < 4; i++)
#pragma unroll
        for (int j = 0; j < 4; j++) acc[i][j] = 0.f;

    for (int k0 = 0; k0 < K; k0 += 16){
        for (int i = tid; i < 1024; i += 256){
            int mm = i >> 4, kk = i & 15;
            int gk = k0 + kk;
            int gm = m0 + mm;
            As[kk][mm] = (gm < M && gk < K) ? A[(size_t)gm*lda + gk] : 0.f;
            int gn = n0 + mm;
            Ws[kk][mm] = (gn < N && gk < K) ? W[(size_t)gn*ldw + gk] : 0.f;
        }
        __syncthreads();
#pragma unroll
        for (int kk = 0; kk < 16; kk++){
            float4 a4 = *(const float4*)&As[kk][ty*4];
            float4 w4 = *(const float4*)&Ws[kk][tx*4];
            float av[4] = {a4.x, a4.y, a4.z, a4.w};
            float wv[4] = {w4.x, w4.y, w4.z, w4.w};
#pragma unroll
            for (int i = 0; i < 4; i++)
#pragma unroll
                for (int j = 0; j < 4; j++) acc[i][j] += av[i]*wv[j];
        }
        __syncthreads();
    }

#pragma unroll
    for (int i = 0; i < 4; i++){
        int gm = m0 + ty*4 + i;
        if (gm >= M) continue;
#pragma unroll
        for (int j = 0; j < 4; j++){
            int gn = n0 + tx*4 + j;
            if (gn >= N) continue;
            float v = acc[i][j] + bias[gn];
            v = fmaxf(v, 0.f) + __logf(1.f + __expf(-fabsf(v)));   // fast softplus
            C[(size_t)gm*(2*DINNER) + 2*gn] = v;                   // du.x
        }
    }
}

// ---------------- depthwise causal conv (k=4) + silu, 2 d per thread ------------
__global__ void k_dwconv(const float* __restrict__ cw, const float* __restrict__ cb){
    int idx = blockIdx.x*256 + threadIdx.x;           // BT*DINNER/2 threads
    int d2 = idx % (DINNER/2);
    int bt = idx / (DINNER/2);
    int d  = d2*2;
    int t  = bt & 511;
    float4 w0 = *(const float4*)&cw[d*4];             // weights for d
    float4 w1 = *(const float4*)&cw[d*4 + 4];         // weights for d+1
    float2 acc = *(const float2*)&cb[d];
    float w0a[4] = {w0.x, w0.y, w0.z, w0.w};
    float w1a[4] = {w1.x, w1.y, w1.z, w1.w};
#pragma unroll
    for (int k = 0; k < 4; k++){
        int tt = t - 3 + k;
        if (tt >= 0){
            float2 xv = *(const float2*)&g_xz[(size_t)(bt - 3 + k)*2*DINNER + d];
            acc.x += w0a[k]*xv.x;
            acc.y += w1a[k]*xv.y;
        }
    }
    float u0 = tf32r(silu_f(acc.x));
    float u1 = tf32r(silu_f(acc.y));
    *(float2*)&g_xinp[(size_t)bt*LDA_OUT + d] = make_float2(u0, u1);
    g_du[(size_t)bt*2*DINNER + 2*d + 1]     = u0;     // du.y for d
    g_du[(size_t)bt*2*DINNER + 2*(d+1) + 1] = u1;     // du.y for d+1
}

// ---------------- selective scan: warp per (b,d), 2 states/lane ----------------
__global__ void k_scan(const float* __restrict__ Alog, const float* __restrict__ Dv){
    int w    = blockIdx.x*4 + (threadIdx.x >> 5);
    int lane = threadIdx.x & 31;
    int b = w & 3;
    int d = w >> 2;

    float A1 = -__expf(Alog[d*64 + lane]);
    float A2 = -__expf(Alog[d*64 + lane + 32]);
    float Dd = Dv[d];
    float h1 = 0.f, h2 = 0.f;

    int r = b*NT;
    for (int t = 0; t < NT; t++, r++){
        float2 du  = *(const float2*)&g_du[(size_t)r*2*DINNER + 2*d];
        float dtv = du.x, uv = du.y;
        float2 B12 = *(const float2*)&g_bc[(size_t)r*128 + 2*lane];
        float2 C12 = *(const float2*)&g_bc[(size_t)r*128 + 64 + 2*lane];
        float dub = dtv*uv;
        h1 = __expf(dtv*A1)*h1 + dub*B12.x;
        h2 = __expf(dtv*A2)*h2 + dub*B12.y;
        float p = h1*C12.x + h2*C12.y;
#pragma unroll
        for (int o = 16; o > 0; o >>= 1) p += __shfl_xor_sync(0xffffffffu, p, o);
        if (lane == 0){
            float zv = g_xz[(size_t)r*2*DINNER + DINNER + d];
            g_yp[(size_t)r*LDA_OUT + d] = tf32r((p + uv*Dd) * silu_f(zv));
        }
    }
}

// ---------------- classifier: warp per (row, class) ----------------
__global__ void k_classifier(const float* __restrict__ ow,
                             const float* __restrict__ ob,
                             float* __restrict__ out){
    int m = blockIdx.x;
    int wid  = threadIdx.x >> 5;
    int lane = threadIdx.x & 31;
    const float* u  = g_unp + (size_t)m*LDA_IN;
    const float* wr = ow + wid*DMODEL;
    float s = 0.f;
    for (int k = lane; k < DMODEL; k += 32) s += u[k]*wr[k];
#pragma unroll
    for (int o = 16; o > 0; o >>= 1) s += __shfl_xor_sync(0xffffffffu, s, o);
    if (lane == 0) out[m*10 + wid] = s + ob[wid];
}

// ---------------- orchestration ----------------
extern "C" void kernel_launch(void* const* d_in, const int* in_sizes, int n_in,
                              void* d_out, int out_size){
    const float* x    = (const float*)d_in[0];
    const float* pw   = (const float*)d_in[1];
    const float* pb   = (const float*)d_in[2];
    const float* c1w  = (const float*)d_in[3];
    const float* c1b  = (const float*)d_in[4];
    const float* c2w  = (const float*)d_in[5];
    const float* c2b  = (const float*)d_in[6];
    const float* c3w  = (const float*)d_in[7];
    const float* c3b  = (const float*)d_in[8];
    const float* lnw  = (const float*)d_in[9];
    const float* lnb  = (const float*)d_in[10];
    const float* ow   = (const float*)d_in[11];
    const float* ob   = (const float*)d_in[12];
    const float* rmsw = (const float*)d_in[13];
    const float* inw  = (const float*)d_in[14];
    const float* dww  = (const float*)d_in[15];
    const float* dwb  = (const float*)d_in[16];
    const float* xpw  = (const float*)d_in[17];
    const float* dtw  = (const float*)d_in[18];
    const float* dtb  = (const float*)d_in[19];
    const float* alog = (const float*)d_in[20];
    const float* dsk  = (const float*)d_in[21];
    const float* opw  = (const float*)d_in[22];

    float *p_unp, *p_xz, *p_xinp, *p_du, *p_yp, *p_h;
    float *p_wi, *p_wo, *p_wx, *p_dtA, *p_bc;
    cudaGetSymbolAddress((void**)&p_unp,  g_unp);
    cudaGetSymbolAddress((void**)&p_xz,   g_xz);
    cudaGetSymbolAddress((void**)&p_xinp, g_xinp);
    cudaGetSymbolAddress((void**)&p_du,   g_du);
    cudaGetSymbolAddress((void**)&p_yp,   g_yp);
    cudaGetSymbolAddress((void**)&p_h,    g_h);
    cudaGetSymbolAddress((void**)&p_wi,   g_wi);
    cudaGetSymbolAddress((void**)&p_wo,   g_wo);
    cudaGetSymbolAddress((void**)&p_wx,   g_wx);
    cudaGetSymbolAddress((void**)&p_dtA,  g_dtA);
    cudaGetSymbolAddress((void**)&p_bc,   g_bc);

    // dynamic-smem opt-in: double-buffered tiles
    const int SMEM8 = 2*(128*36 + 128*36)*4;   // 73728 B for NJ=8
    const int SMEM4 = 2*(128*36 +  64*36)*4;   // 55296 B for NJ=4
    cudaFuncSetAttribute(k_mma128<8>, cudaFuncAttributeMaxDynamicSharedMemorySize, SMEM8);
    cudaFuncSetAttribute(k_mma128<4>, cudaFuncAttributeMaxDynamicSharedMemorySize, SMEM4);

    // weight repacks into padded layout, rna tf32 rounding (pads stay zero)
    k_packw<<<(2*2*DINNER*DMODEL + 255)/256, 256>>>(inw, p_wi, 2*2*DINNER, DMODEL, LDA_IN);
    k_packw<<<(2*DMODEL*DINNER + 255)/256, 256>>>(opw, p_wo, 2*DMODEL, DINNER, LDA_OUT);
    k_packw<<<(2*XPROJ_N*DINNER + 255)/256, 256>>>(xpw, p_wx, 2*XPROJ_N, DINNER, LDA_OUT);

    k_xt<<<dim3(16, 2, 4), dim3(32, 32)>>>(x);
    k_pointconv<<<1024, 256>>>(pw, pb);
    k_conv<3> <<<512, 256>>>(c1w, c1b, 0);
    k_conv<9> <<<512, 256>>>(c2w, c2b, 256);
    k_conv<27><<<512, 256>>>(c3w, c3b, 512);
    k_transpose<<<dim3(16, 24, 4), dim3(32, 32)>>>();
    k_pe<<<8, 256>>>(x);

    for (int l = 0; l < 2; l++){
        k_rmsnorm<<<2048, 256>>>(rmsw + l*DMODEL);
        // xz = un @ Wi^T       (2048 x 3076, K=769)  tf32 mma BN=128, 400 blocks
        k_mma128<8><<<dim3(25, 16), 256, SMEM8>>>(p_unp, LDA_IN,
                                        p_wi + (size_t)l*2*DINNER*LDA_IN, LDA_IN,
                                        p_xz, 2*DINNER,
                                        BT, 2*DINNER, DMODEL, 0, nullptr);
        k_dwconv<<<6152, 256>>>(dww + l*DINNER*4, dwb + l*DINNER);
        // dbc = xin @ Wx^T     (2048 x 177, K=1538)  tf32 mma, scatter epilogue
        k_mma128<4><<<dim3(3, 16), 256, SMEM4>>>(p_xinp, LDA_OUT,
                                        p_wx + (size_t)l*XPROJ_N*LDA_OUT, LDA_OUT,
                                        p_dtA, 64,
                                        BT, XPROJ_N, DINNER, 3, p_bc);
        // dt = softplus(dtA @ Wdt^T + bdt) -> g_du.x   (K=49, fp32 64x64)
        k_sgemm64<<<dim3(25, 32), 256>>>(p_dtA, 64,
                                         dtw + (size_t)l*DINNER*DTRANK, DTRANK,
                                         p_du,
                                         BT, DINNER, DTRANK, dtb + l*DINNER);
        k_scan<<<1538, 128>>>(alog + (size_t)l*DINNER*DSTATE, dsk + l*DINNER);
        // h += y @ Wo^T        (2048 x 769, K=1538)  tf32 mma BN=64, 208 blocks
        k_mma128<4><<<dim3(13, 16), 256, SMEM4>>>(p_yp, LDA_OUT,
                                       p_wo + (size_t)l*DMODEL*LDA_OUT, LDA_OUT,
                                       p_h, DMODEL,
                                       BT, DMODEL, DINNER, 2, nullptr);
    }

    k_layernorm<<<2048, 256>>>(lnw, lnb);
    k_classifier<<<2048, 320>>>(ow, ob, (float*)d_out);
}

// round 17
// speedup vs baseline: 1.0912x; 1.0824x over previous
#include <cuda_runtime.h>
#include <math.h>
#include <stdint.h>

#define NB 4
#define NT 512
#define DMODEL 769
#define DINNER 1538
#define DSTATE 64
#define DTRANK 49
#define BT (NB*NT)            // 2048 rows
#define XPROJ_N 177           // DT_RANK + 2*D_STATE
#define LDA_IN 800            // padded ld (25 k-tiles of 32)
#define LDA_OUT 1568          // padded ld (49 k-tiles of 32)

// ---------------- scratch (static device globals; zero-initialized) -------------
__device__ float g_xT [NB*64*NT];
__device__ float g_h0 [NB*128*NT];                        // pointconv out (b,c,t), rna
__device__ float g_h  [BT*DMODEL];
__device__ __align__(16) float g_unp [BT*LDA_IN];         // rmsnorm out (rna) / layernorm out
__device__ __align__(16) float g_wi  [2*2*DINNER*LDA_IN]; // in_proj W padded (rna)
__device__ __align__(16) float g_wo  [2*DMODEL*LDA_OUT];  // out_proj W padded (rna)
__device__ __align__(16) float g_wx  [2*XPROJ_N*LDA_OUT]; // x_proj W padded (rna)
__device__ __align__(16) float g_wc3 [256*128*3];         // conv weights rna
__device__ __align__(16) float g_wc9 [256*128*9];
__device__ __align__(16) float g_wc27[256*128*27];
__device__ __align__(16) float g_xinp[BT*LDA_OUT];        // dwconv out, padded (rna)
__device__ __align__(16) float g_yp  [BT*LDA_OUT];        // scan out, padded (rna)
__device__ __align__(16) float g_dtA [BT*64];             // x_proj dt-cols (rna), padded
__device__ __align__(16) float g_bc  [BT*128];            // B/C interleaved for scan
__device__ __align__(16) float g_du  [BT*2*DINNER];       // (dt, u) interleaved for scan
__device__ float g_xz [BT*2*DINNER];

__device__ __forceinline__ float silu_f(float v){ return v / (1.f + __expf(-v)); }
__device__ __forceinline__ float tf32r(float v){
    uint32_t r; asm("cvt.rna.tf32.f32 %0, %1;" : "=r"(r) : "f"(v));
    return __uint_as_float(r);
}

// ---- tf32 mma (operands pre-rounded by producers) ----
__device__ __forceinline__ void mma_tf32(float* c, const uint32_t* a, const uint32_t* b){
    asm("mma.sync.aligned.m16n8k8.row.col.f32.tf32.tf32.f32 "
        "{%0,%1,%2,%3}, {%4,%5,%6,%7}, {%8,%9}, {%0,%1,%2,%3};"
        : "+f"(c[0]), "+f"(c[1]), "+f"(c[2]), "+f"(c[3])
        : "r"(a[0]), "r"(a[1]), "r"(a[2]), "r"(a[3]), "r"(b[0]), "r"(b[1]));
}

// ---------------- weight repack (rna tf32); ldd may equal K (plain copy) --------
__global__ void k_packw(const float* __restrict__ src, float* __restrict__ dst,
                        int rows, int K, int ldd){
    int idx = blockIdx.x*256 + threadIdx.x;
    if (idx >= rows*K) return;
    int r = idx / K, c = idx - r*K;
    dst[(size_t)r*ldd + c] = tf32r(src[idx]);
}

// ---------------- x (B,T,65) -> g_xT (B,64,T) ----------------
__global__ void k_xt(const float* __restrict__ x){
    __shared__ float tile[32][33];
    int b  = blockIdx.z;
    int t0 = blockIdx.x*32, c0 = blockIdx.y*32;
    int tx = threadIdx.x, ty = threadIdx.y;
    tile[ty][tx] = x[(b*NT + t0 + ty)*65 + c0 + tx];
    __syncthreads();
    g_xT[(b*64 + c0 + ty)*NT + t0 + tx] = tile[tx][ty];
}

// ---------------- front: pointwise conv (64->128) + silu, rna out ---------------
__global__ void k_pointconv(const float* __restrict__ pw,
                            const float* __restrict__ pb){
    int idx = blockIdx.x*256 + threadIdx.x;
    int t = idx & 511;
    int c = (idx >> 9) & 127;
    int b = idx >> 16;
    const float* xr = g_xT + b*64*NT + t;
    const float* wr = pw + c*64;
    float acc = pb[c];
#pragma unroll
    for (int i = 0; i < 64; i++) acc += xr[i*NT]*wr[i];
    g_h0[(b*128 + c)*NT + t] = tf32r(silu_f(acc));
}

// ---------------- conv as tf32 mma: out = silu(im2col(x) @ Wc^T + bias) ---------
// K = 128*KS (divisible by 32). Block tile 128(t-rows) x 64(oc). 8 warps, NJ=4.
// A staged from g_h0 (b,c,t): thread's 16 consecutive cols -> consecutive t.
// Writes directly into g_h[., ocBase + oc] (fused transpose).
template<int KS>
__global__ void __launch_bounds__(256, 2)
k_convmma(const float* __restrict__ Wc,
          const float* __restrict__ bias,
          int ocBase){
    const int K = 128*KS;
    __shared__ __align__(16) float As[128][36];
    __shared__ __align__(16) float Ws[64][36];

    const int tid  = threadIdx.x;
    const int lane = tid & 31;
    const int wid  = tid >> 5;
    const int warp_m = wid & 3, warp_n = wid >> 2;   // warp_n 0..1
    const int m0 = blockIdx.y*128, n0 = blockIdx.x*64;
    const int b  = m0 >> 9, t0 = m0 & 511;
    const int pad = (KS - 1)/2;

    const int sr  = tid >> 1;           // 0..127 (row = t_local)
    const int skb = (tid & 1) * 16;

    const bool stW = (sr < 64);
    const float* Wrow  = Wc + (size_t)(n0 + sr)*K + skb;
    const float* xbase = g_h0 + (size_t)b*128*NT;

    float acc[2][4][4];
#pragma unroll
    for (int i = 0; i < 2; i++)
#pragma unroll
        for (int j = 0; j < 4; j++)
#pragma unroll
            for (int q = 0; q < 4; q++) acc[i][j][q] = 0.f;

    const int nk = K/32;
    float ra[16];
    float4 rb4[4];

    // prefetch tile 0
#pragma unroll
    for (int q = 0; q < 16; q++){
        int col = skb + q;
        int ic = col / KS, k = col - ic*KS;
        int ts = t0 + sr + k - pad;
        ra[q] = (ts >= 0 && ts < NT) ? xbase[ic*NT + ts] : 0.f;
    }
    if (stW){
#pragma unroll
        for (int q = 0; q < 4; q++) rb4[q] = ((const float4*)Wrow)[q];
    }

    const int r_f = lane >> 2;
    const int c_f = lane & 3;

    for (int kt = 0; kt < nk; kt++){
        __syncthreads();
#pragma unroll
        for (int q = 0; q < 16; q++) As[sr][skb + q] = ra[q];
        if (stW){
#pragma unroll
            for (int q = 0; q < 4; q++)
                *(float4*)&Ws[sr][skb + q*4] = rb4[q];
        }
        __syncthreads();

        if (kt + 1 < nk){
            int c0 = (kt + 1)*32 + skb;
#pragma unroll
            for (int q = 0; q < 16; q++){
                int col = c0 + q;
                int ic = col / KS, k = col - ic*KS;
                int ts = t0 + sr + k - pad;
                ra[q] = (ts >= 0 && ts < NT) ? xbase[ic*NT + ts] : 0.f;
            }
            if (stW){
#pragma unroll
                for (int q = 0; q < 4; q++)
                    rb4[q] = ((const float4*)(Wrow + (kt + 1)*32))[q];
            }
        }

#pragma unroll
        for (int kch = 0; kch < 4; kch++){
            uint32_t af[2][4], bf[4][2];
#pragma unroll
            for (int i = 0; i < 2; i++){
                const uint32_t* ar = (const uint32_t*)&As[warp_m*32 + i*16 + r_f][kch*8 + c_f];
                af[i][0] = ar[0];
                af[i][1] = ar[8*36];
                af[i][2] = ar[4];
                af[i][3] = ar[8*36 + 4];
            }
#pragma unroll
            for (int j = 0; j < 4; j++){
                const uint32_t* br = (const uint32_t*)&Ws[warp_n*32 + j*8 + r_f][kch*8 + c_f];
                bf[j][0] = br[0];
                bf[j][1] = br[4];
            }
#pragma unroll
            for (int i = 0; i < 2; i++)
#pragma unroll
                for (int j = 0; j < 4; j++) mma_tf32(acc[i][j], af[i], bf[j]);
        }
    }

    const int r_c = lane >> 2, c_c = (lane & 3)*2;
#pragma unroll
    for (int i = 0; i < 2; i++){
        int gm0 = m0 + warp_m*32 + i*16 + r_c;
#pragma unroll
        for (int j = 0; j < 4; j++){
            int gn0 = n0 + warp_n*32 + j*8 + c_c;
#pragma unroll
            for (int h = 0; h < 2; h++){
                int gm = gm0 + h*8;
#pragma unroll
                for (int e = 0; e < 2; e++){
                    int gn = gn0 + e;
                    float v = acc[i][j][2*h + e] + bias[gn];
                    g_h[(size_t)gm*DMODEL + ocBase + gn] = silu_f(v);
                }
            }
        }
    }
}

__global__ void k_pe(const float* __restrict__ x){
    int i = blockIdx.x*256 + threadIdx.x;
    if (i >= BT) return;
    g_h[i*DMODEL + 768] = x[i*65 + 64];
}

// ---------------- rmsnorm (rna tf32 out, padded) / layernorm (exact) ------------
__global__ void k_rmsnorm(const float* __restrict__ w){
    int m = blockIdx.x, tid = threadIdx.x;
    const float* row = g_h + m*DMODEL;
    float s = 0.f;
    for (int k = tid; k < DMODEL; k += 256){ float v = row[k]; s += v*v; }
#pragma unroll
    for (int o = 16; o > 0; o >>= 1) s += __shfl_xor_sync(0xffffffffu, s, o);
    __shared__ float red[8];
    if ((tid & 31) == 0) red[tid >> 5] = s;
    __syncthreads();
    s = red[0]+red[1]+red[2]+red[3]+red[4]+red[5]+red[6]+red[7];
    float sc = rsqrtf(s/769.f + 1e-6f);
    float* o = g_unp + (size_t)m*LDA_IN;
    for (int k = tid; k < DMODEL; k += 256) o[k] = tf32r(row[k]*sc*w[k]);
}

__global__ void k_layernorm(const float* __restrict__ w, const float* __restrict__ bb){
    int m = blockIdx.x, tid = threadIdx.x;
    const float* row = g_h + m*DMODEL;
    float s1 = 0.f, s2 = 0.f;
    for (int k = tid; k < DMODEL; k += 256){ float v = row[k]; s1 += v; s2 += v*v; }
#pragma unroll
    for (int o = 16; o > 0; o >>= 1){
        s1 += __shfl_xor_sync(0xffffffffu, s1, o);
        s2 += __shfl_xor_sync(0xffffffffu, s2, o);
    }
    __shared__ float r1[8], r2[8];
    if ((tid & 31) == 0){ r1[tid >> 5] = s1; r2[tid >> 5] = s2; }
    __syncthreads();
    s1 = 0.f; s2 = 0.f;
#pragma unroll
    for (int i = 0; i < 8; i++){ s1 += r1[i]; s2 += r2[i]; }
    float mean = s1/769.f;
    float var  = s2/769.f - mean*mean;
    float istd = rsqrtf(var + 1e-5f);
    float* o = g_unp + (size_t)m*LDA_IN;
    for (int k = tid; k < DMODEL; k += 256)
        o[k] = (row[k] - mean)*istd*w[k] + bb[k];
}

// ---------------- tf32 MMA GEMM 128xBNx32, conflict-free smem, double-buffered --
// NJ = BN/16. Padded zero-filled operands. Dynamic smem:
//   A[2][128*36] then W[2][NJ*16*36] floats.
// epi: 0 = store, 2 = C += acc,
//      3 = x_proj scatter: gn<49 -> C (dtA, ld 64, rna); else B/C interleave -> C2
template<int NJ>
__global__ void __launch_bounds__(256, 2)
k_mma128(const float* __restrict__ A, int lda,
         const float* __restrict__ W, int ldw,
         float* __restrict__ C, int ldc,
         int M, int N, int K, int epi,
         float* __restrict__ C2){
    extern __shared__ float smem[];
    const int BN   = NJ*16;
    const int A_SZ = 128*36;
    const int W_SZ = BN*36;
    float* Abuf = smem;
    float* Wbuf = smem + 2*A_SZ;

    const int tid  = threadIdx.x;
    const int lane = tid & 31;
    const int wid  = tid >> 5;
    const int warp_m = wid & 3, warp_n = wid >> 2;
    const int m0 = blockIdx.y*128, n0 = blockIdx.x*BN;

    const int sr  = tid >> 1;
    const int skb = (tid & 1) * 16;

    const bool okA = (m0 + sr) < M;
    const bool stW = (sr < BN);
    const bool okW = stW && ((n0 + sr) < N);
    const float* Arow = A + (size_t)(m0 + sr)*lda + skb;
    const float* Wrow = W + (size_t)(n0 + sr)*ldw + skb;

    float acc[2][NJ][4];
#pragma unroll
    for (int i = 0; i < 2; i++)
#pragma unroll
        for (int j = 0; j < NJ; j++)
#pragma unroll
            for (int q = 0; q < 4; q++) acc[i][j][q] = 0.f;

    const int nk = (K + 31) >> 5;
    float4 ra4[4], rb4[4];

#pragma unroll
    for (int q = 0; q < 4; q++){
        ra4[q] = okA ? ((const float4*)Arow)[q] : make_float4(0.f,0.f,0.f,0.f);
        rb4[q] = okW ? ((const float4*)Wrow)[q] : make_float4(0.f,0.f,0.f,0.f);
    }
#pragma unroll
    for (int q = 0; q < 4; q++)
        *(float4*)&Abuf[sr*36 + skb + q*4] = ra4[q];
    if (stW){
#pragma unroll
        for (int q = 0; q < 4; q++)
            *(float4*)&Wbuf[sr*36 + skb + q*4] = rb4[q];
    }
    __syncthreads();

    const int r_f = lane >> 2;
    const int c_f = lane & 3;

    int buf = 0;
    for (int kt = 0; kt < nk; kt++){
        if (kt + 1 < nk){
            int k0 = (kt + 1)*32;
#pragma unroll
            for (int q = 0; q < 4; q++){
                ra4[q] = okA ? ((const float4*)(Arow + k0))[q] : make_float4(0.f,0.f,0.f,0.f);
                rb4[q] = okW ? ((const float4*)(Wrow + k0))[q] : make_float4(0.f,0.f,0.f,0.f);
            }
        }

        const float* Ab = Abuf + buf*A_SZ;
        const float* Wb = Wbuf + buf*W_SZ;
#pragma unroll
        for (int kch = 0; kch < 4; kch++){
            uint32_t af[2][4], bf[NJ][2];
#pragma unroll
            for (int i = 0; i < 2; i++){
                const uint32_t* ar = (const uint32_t*)&Ab[(warp_m*32 + i*16 + r_f)*36 + kch*8 + c_f];
                af[i][0] = ar[0];
                af[i][1] = ar[8*36];
                af[i][2] = ar[4];
                af[i][3] = ar[8*36 + 4];
            }
#pragma unroll
            for (int j = 0; j < NJ; j++){
                const uint32_t* br = (const uint32_t*)&Wb[(warp_n*NJ*8 + j*8 + r_f)*36 + kch*8 + c_f];
                bf[j][0] = br[0];
                bf[j][1] = br[4];
            }
#pragma unroll
            for (int i = 0; i < 2; i++)
#pragma unroll
                for (int j = 0; j < NJ; j++) mma_tf32(acc[i][j], af[i], bf[j]);
        }

        if (kt + 1 < nk){
            int nb = buf ^ 1;
            float* An = Abuf + nb*A_SZ;
            float* Wn = Wbuf + nb*W_SZ;
#pragma unroll
            for (int q = 0; q < 4; q++)
                *(float4*)&An[sr*36 + skb + q*4] = ra4[q];
            if (stW){
#pragma unroll
                for (int q = 0; q < 4; q++)
                    *(float4*)&Wn[sr*36 + skb + q*4] = rb4[q];
            }
            __syncthreads();
            buf = nb;
        }
    }

    const int r_c = lane >> 2, c_c = (lane & 3)*2;
#pragma unroll
    for (int i = 0; i < 2; i++){
        int gmA0 = m0 + warp_m*32 + i*16 + r_c;
#pragma unroll
        for (int j = 0; j < NJ; j++){
            int gn0 = n0 + warp_n*(NJ*8) + j*8 + c_c;
#pragma unroll
            for (int h = 0; h < 2; h++){
                int gm = gmA0 + h*8;
                if (gm >= M) continue;
#pragma unroll
                for (int e = 0; e < 2; e++){
                    int gn = gn0 + e;
                    if (gn >= N) continue;
                    float v = acc[i][j][2*h + e];
                    if (epi == 0){
                        C[(size_t)gm*ldc + gn] = v;
                    } else if (epi == 2){
                        C[(size_t)gm*ldc + gn] += v;
                    } else {  // epi == 3: x_proj scatter
                        if (gn < DTRANK){
                            C[(size_t)gm*64 + gn] = tf32r(v);
                        } else if (gn < DTRANK + DSTATE){
                            int nb2 = gn - DTRANK;
                            int slot = (nb2 < 32) ? 2*nb2 : 2*(nb2 - 32) + 1;
                            C2[(size_t)gm*128 + slot] = v;
                        } else {
                            int nc = gn - DTRANK - DSTATE;
                            int slot = 64 + ((nc < 32) ? 2*nc : 2*(nc - 32) + 1);
                            C2[(size_t)gm*128 + slot] = v;
                        }
                    }
                }
            }
        }
    }
}

// ---------------- SGEMM 64x64 fp32 (dt GEMM): bias + fast softplus --------------
// writes dt into g_du at stride 2 (slot .x)
__global__ void k_sgemm64(const float* __restrict__ A, int lda,
                          const float* __restrict__ W, int ldw,
                          float* __restrict__ C,
                          int M, int N, int K,
                          const float* __restrict__ bias){
    __shared__ __align__(16) float As[16][68];
    __shared__ __align__(16) float Ws[16][68];
    const int tid = threadIdx.x;
    const int m0 = blockIdx.y*64, n0 = blockIdx.x*64;
    const int tx = tid & 15, ty = tid >> 4;

    float acc[4][4];
#pragma unroll
    for (int i = 0; i < 4; i++)
#pragma unroll
        for (int j = 0; j < 4; j++) acc[i][j] = 0.f;

    for (int k0 = 0; k0 < K; k0 += 16){
        for (int i = tid; i < 1024; i += 256){
            int mm = i >> 4, kk = i & 15;
            int gk = k0 + kk;
            int gm = m0 + mm;
            As[kk][mm] = (gm < M && gk < K) ? A[(size_t)gm*lda + gk] : 0.f;
            int gn = n0 + mm;
            Ws[kk][mm] = (gn < N && gk < K) ? W[(size_t)gn*ldw + gk] : 0.f;
        }
        __syncthreads();
#pragma unroll
        for (int kk = 0; kk < 16; kk++){
            float4 a4 = *(const float4*)&As[kk][ty*4];
            float4 w4 = *(const float4*)&Ws[kk][tx*4];
            float av[4] = {a4.x, a4.y, a4.z, a4.w};
            float wv[4] = {w4.x, w4.y, w4.z, w4.w};
#pragma unroll
            for (int i = 0; i < 4; i++)
#pragma unroll
                for (int j = 0; j < 4; j++) acc[i][j] += av[i]*wv[j];
        }
        __syncthreads();
    }

#pragma unroll
    for (int i = 0; i < 4; i++){
        int gm = m0 + ty*4 + i;
        if (gm >= M) continue;
#pragma unroll
        for (int j = 0; j < 4; j++){
            int gn = n0 + tx*4 + j;
            if (gn >= N) continue;
            float v = acc[i][j] + bias[gn];
            v = fmaxf(v, 0.f) + __logf(1.f + __expf(-fabsf(v)));   // fast softplus
            C[(size_t)gm*(2*DINNER) + 2*gn] = v;                   // du.x
        }
    }
}

// ---------------- depthwise causal conv (k=4) + silu, 2 d per thread ------------
__global__ void k_dwconv(const float* __restrict__ cw, const float* __restrict__ cb){
    int idx = blockIdx.x*256 + threadIdx.x;           // BT*DINNER/2 threads
    int d2 = idx % (DINNER/2);
    int bt = idx / (DINNER/2);
    int d  = d2*2;
    int t  = bt & 511;
    float4 w0 = *(const float4*)&cw[d*4];
    float4 w1 = *(const float4*)&cw[d*4 + 4];
    float2 acc = *(const float2*)&cb[d];
    float w0a[4] = {w0.x, w0.y, w0.z, w0.w};
    float w1a[4] = {w1.x, w1.y, w1.z, w1.w};
#pragma unroll
    for (int k = 0; k < 4; k++){
        int tt = t - 3 + k;
        if (tt >= 0){
            float2 xv = *(const float2*)&g_xz[(size_t)(bt - 3 + k)*2*DINNER + d];
            acc.x += w0a[k]*xv.x;
            acc.y += w1a[k]*xv.y;
        }
    }
    float u0 = tf32r(silu_f(acc.x));
    float u1 = tf32r(silu_f(acc.y));
    *(float2*)&g_xinp[(size_t)bt*LDA_OUT + d] = make_float2(u0, u1);
    g_du[(size_t)bt*2*DINNER + 2*d + 1]     = u0;
    g_du[(size_t)bt*2*DINNER + 2*(d+1) + 1] = u1;
}

// ---------------- selective scan: warp per (b,d), 2 states/lane ----------------
__global__ void k_scan(const float* __restrict__ Alog, const float* __restrict__ Dv){
    int w    = blockIdx.x*4 + (threadIdx.x >> 5);
    int lane = threadIdx.x & 31;
    int b = w & 3;
    int d = w >> 2;

    float A1 = -__expf(Alog[d*64 + lane]);
    float A2 = -__expf(Alog[d*64 + lane + 32]);
    float Dd = Dv[d];
    float h1 = 0.f, h2 = 0.f;

    int r = b*NT;
    for (int t = 0; t < NT; t++, r++){
        float2 du  = *(const float2*)&g_du[(size_t)r*2*DINNER + 2*d];
        float dtv = du.x, uv = du.y;
        float2 B12 = *(const float2*)&g_bc[(size_t)r*128 + 2*lane];
        float2 C12 = *(const float2*)&g_bc[(size_t)r*128 + 64 + 2*lane];
        float dub = dtv*uv;
        h1 = __expf(dtv*A1)*h1 + dub*B12.x;
        h2 = __expf(dtv*A2)*h2 + dub*B12.y;
        float p = h1*C12.x + h2*C12.y;
#pragma unroll
        for (int o = 16; o > 0; o >>= 1) p += __shfl_xor_sync(0xffffffffu, p, o);
        if (lane == 0){
            float zv = g_xz[(size_t)r*2*DINNER + DINNER + d];
            g_yp[(size_t)r*LDA_OUT + d] = tf32r((p + uv*Dd) * silu_f(zv));
        }
    }
}

// ---------------- classifier: warp per (row, class) ----------------
__global__ void k_classifier(const float* __restrict__ ow,
                             const float* __restrict__ ob,
                             float* __restrict__ out){
    int m = blockIdx.x;
    int wid  = threadIdx.x >> 5;
    int lane = threadIdx.x & 31;
    const float* u  = g_unp + (size_t)m*LDA_IN;
    const float* wr = ow + wid*DMODEL;
    float s = 0.f;
    for (int k = lane; k < DMODEL; k += 32) s += u[k]*wr[k];
#pragma unroll
    for (int o = 16; o > 0; o >>= 1) s += __shfl_xor_sync(0xffffffffu, s, o);
    if (lane == 0) out[m*10 + wid] = s + ob[wid];
}

// ---------------- orchestration ----------------
extern "C" void kernel_launch(void* const* d_in, const int* in_sizes, int n_in,
                              void* d_out, int out_size){
    const float* x    = (const float*)d_in[0];
    const float* pw   = (const float*)d_in[1];
    const float* pb   = (const float*)d_in[2];
    const float* c1w  = (const float*)d_in[3];
    const float* c1b  = (const float*)d_in[4];
    const float* c2w  = (const float*)d_in[5];
    const float* c2b  = (const float*)d_in[6];
    const float* c3w  = (const float*)d_in[7];
    const float* c3b  = (const float*)d_in[8];
    const float* lnw  = (const float*)d_in[9];
    const float* lnb  = (const float*)d_in[10];
    const float* ow   = (const float*)d_in[11];
    const float* ob   = (const float*)d_in[12];
    const float* rmsw = (const float*)d_in[13];
    const float* inw  = (const float*)d_in[14];
    const float* dww  = (const float*)d_in[15];
    const float* dwb  = (const float*)d_in[16];
    const float* xpw  = (const float*)d_in[17];
    const float* dtw  = (const float*)d_in[18];
    const float* dtb  = (const float*)d_in[19];
    const float* alog = (const float*)d_in[20];
    const float* dsk  = (const float*)d_in[21];
    const float* opw  = (const float*)d_in[22];

    float *p_unp, *p_xz, *p_xinp, *p_du, *p_yp, *p_h;
    float *p_wi, *p_wo, *p_wx, *p_dtA, *p_bc, *p_wc3, *p_wc9, *p_wc27;
    cudaGetSymbolAddress((void**)&p_unp,  g_unp);
    cudaGetSymbolAddress((void**)&p_xz,   g_xz);
    cudaGetSymbolAddress((void**)&p_xinp, g_xinp);
    cudaGetSymbolAddress((void**)&p_du,   g_du);
    cudaGetSymbolAddress((void**)&p_yp,   g_yp);
    cudaGetSymbolAddress((void**)&p_h,    g_h);
    cudaGetSymbolAddress((void**)&p_wi,   g_wi);
    cudaGetSymbolAddress((void**)&p_wo,   g_wo);
    cudaGetSymbolAddress((void**)&p_wx,   g_wx);
    cudaGetSymbolAddress((void**)&p_dtA,  g_dtA);
    cudaGetSymbolAddress((void**)&p_bc,   g_bc);
    cudaGetSymbolAddress((void**)&p_wc3,  g_wc3);
    cudaGetSymbolAddress((void**)&p_wc9,  g_wc9);
    cudaGetSymbolAddress((void**)&p_wc27, g_wc27);

    // dynamic-smem opt-in: double-buffered tiles for k_mma128
    const int SMEM8 = 2*(128*36 + 128*36)*4;
    const int SMEM4 = 2*(128*36 +  64*36)*4;
    cudaFuncSetAttribute(k_mma128<8>, cudaFuncAttributeMaxDynamicSharedMemorySize, SMEM8);
    cudaFuncSetAttribute(k_mma128<4>, cudaFuncAttributeMaxDynamicSharedMemorySize, SMEM4);

    // weight repacks, rna tf32 rounding
    k_packw<<<(2*2*DINNER*DMODEL + 255)/256, 256>>>(inw, p_wi, 2*2*DINNER, DMODEL, LDA_IN);
    k_packw<<<(2*DMODEL*DINNER + 255)/256, 256>>>(opw, p_wo, 2*DMODEL, DINNER, LDA_OUT);
    k_packw<<<(2*XPROJ_N*DINNER + 255)/256, 256>>>(xpw, p_wx, 2*XPROJ_N, DINNER, LDA_OUT);
    k_packw<<<(256*128*3  + 255)/256, 256>>>(c1w, p_wc3,  256, 128*3,  128*3);
    k_packw<<<(256*128*9  + 255)/256, 256>>>(c2w, p_wc9,  256, 128*9,  128*9);
    k_packw<<<(256*128*27 + 255)/256, 256>>>(c3w, p_wc27, 256, 128*27, 128*27);

    k_xt<<<dim3(16, 2, 4), dim3(32, 32)>>>(x);
    k_pointconv<<<1024, 256>>>(pw, pb);
    // convs as tf32 mma, writing directly into g_h (fused transpose)
    k_convmma<3> <<<dim3(4, 16), 256>>>(p_wc3,  c1b, 0);
    k_convmma<9> <<<dim3(4, 16), 256>>>(p_wc9,  c2b, 256);
    k_convmma<27><<<dim3(4, 16), 256>>>(p_wc27, c3b, 512);
    k_pe<<<8, 256>>>(x);

    for (int l = 0; l < 2; l++){
        k_rmsnorm<<<2048, 256>>>(rmsw + l*DMODEL);
        // xz = un @ Wi^T       (2048 x 3076, K=769)  tf32 mma BN=128, 400 blocks
        k_mma128<8><<<dim3(25, 16), 256, SMEM8>>>(p_unp, LDA_IN,
                                        p_wi + (size_t)l*2*DINNER*LDA_IN, LDA_IN,
                                        p_xz, 2*DINNER,
                                        BT, 2*DINNER, DMODEL, 0, nullptr);
        k_dwconv<<<6152, 256>>>(dww + l*DINNER*4, dwb + l*DINNER);
        // dbc = xin @ Wx^T     (2048 x 177, K=1538)  tf32 mma, scatter epilogue
        k_mma128<4><<<dim3(3, 16), 256, SMEM4>>>(p_xinp, LDA_OUT,
                                        p_wx + (size_t)l*XPROJ_N*LDA_OUT, LDA_OUT,
                                        p_dtA, 64,
                                        BT, XPROJ_N, DINNER, 3, p_bc);
        // dt = softplus(dtA @ Wdt^T + bdt) -> g_du.x   (K=49, fp32 64x64)
        k_sgemm64<<<dim3(25, 32), 256>>>(p_dtA, 64,
                                         dtw + (size_t)l*DINNER*DTRANK, DTRANK,
                                         p_du,
                                         BT, DINNER, DTRANK, dtb + l*DINNER);
        k_scan<<<1538, 128>>>(alog + (size_t)l*DINNER*DSTATE, dsk + l*DINNER);
        // h += y @ Wo^T        (2048 x 769, K=1538)  tf32 mma BN=64, 208 blocks
        k_mma128<4><<<dim3(13, 16), 256, SMEM4>>>(p_yp, LDA_OUT,
                                       p_wo + (size_t)l*DMODEL*LDA_OUT, LDA_OUT,
                                       p_h, DMODEL,
                                       BT, DMODEL, DINNER, 2, nullptr);
    }

    k_layernorm<<<2048, 256>>>(lnw, lnb);
    k_classifier<<<2048, 320>>>(ow, ob, (float*)d_out);
}